// round 1
// baseline (speedup 1.0000x reference)
#include <cuda_runtime.h>
#include <math.h>
#include <float.h>

#define NB 2
#define NN 4096
#define NC 128
#define NK 8

#define NORMC  (-9.010913347279289f)   // -log(8192)
#define LOGMC  (-0.6931471805599453f)  // log(4096) - log(8192)

// -------- scratch (static device globals; no allocation) --------
__device__ float g_nA[NB * NN * NC];
__device__ float g_nB[NB * NN * NC];
__device__ float g_ST[(size_t)NB * NN * NN];   // 20 * sim^T  (134 MB)
__device__ float g_u[NB * (NN + 1)];
__device__ float g_v[NB * (NN + 1)];
__device__ float g_tkv[NB * NN * NK];
__device__ int   g_tki[NB * NN * NK];
__device__ float g_tkp[NB * NN * NK * 2];
__device__ float g_geo[NB * NN * NK];

// -------- reduction helpers (blockDim == 256) --------
__device__ __forceinline__ float warpMaxF(float v) {
#pragma unroll
    for (int o = 16; o; o >>= 1) v = fmaxf(v, __shfl_xor_sync(0xffffffffu, v, o));
    return v;
}
__device__ __forceinline__ float warpSumF(float v) {
#pragma unroll
    for (int o = 16; o; o >>= 1) v += __shfl_xor_sync(0xffffffffu, v, o);
    return v;
}
__device__ __forceinline__ float blockReduceMax(float v, float* sw) {
    v = warpMaxF(v);
    int wid = threadIdx.x >> 5, lane = threadIdx.x & 31;
    __syncthreads();                       // protect prior use of sw
    if (lane == 0) sw[wid] = v;
    __syncthreads();
    if (wid == 0) {
        float x = (lane < 8) ? sw[lane] : -FLT_MAX;
        x = warpMaxF(x);
        if (lane == 0) sw[0] = x;
    }
    __syncthreads();
    return sw[0];
}
__device__ __forceinline__ float blockReduceSum(float v, float* sw) {
    v = warpSumF(v);
    int wid = threadIdx.x >> 5, lane = threadIdx.x & 31;
    __syncthreads();
    if (lane == 0) sw[wid] = v;
    __syncthreads();
    if (wid == 0) {
        float x = (lane < 8) ? sw[lane] : 0.f;
        x = warpSumF(x);
        if (lane == 0) sw[0] = x;
    }
    __syncthreads();
    return sw[0];
}

// -------- init u = v = 0 --------
__global__ void zero_uv_kernel() {
    int t = blockIdx.x * blockDim.x + threadIdx.x;
    if (t < NB * (NN + 1)) { g_u[t] = 0.f; g_v[t] = 0.f; }
}

// -------- row L2 normalize (warp per row; rows 0..8191=A, 8192..16383=B) --------
__global__ void __launch_bounds__(256) normalize_kernel(const float* __restrict__ fA,
                                                        const float* __restrict__ fB) {
    int gw = (blockIdx.x * blockDim.x + threadIdx.x) >> 5;
    int lane = threadIdx.x & 31;
    if (gw >= 2 * NB * NN) return;
    int row = gw & (NB * NN - 1);
    const float* src = (gw < NB * NN) ? fA : fB;
    float* dst = (gw < NB * NN) ? g_nA : g_nB;
    const float* p = src + (size_t)row * NC;
    float x[4]; float ss = 0.f;
#pragma unroll
    for (int l = 0; l < 4; l++) { x[l] = p[lane + l * 32]; ss += x[l] * x[l]; }
    ss = warpSumF(ss);
    float sc = 1.f / fmaxf(sqrtf(ss), 1e-12f);
    float* q = dst + (size_t)row * NC;
#pragma unroll
    for (int l = 0; l < 4; l++) q[lane + l * 32] = x[l] * sc;
}

// -------- SIMT FP32 GEMM: sim[b,m,n] = sum_c nA[b,m,c]*nB[b,n,c] --------
#define BM 128
#define BN 128
#define BKK 16
__global__ void __launch_bounds__(256) gemm_kernel(float* __restrict__ C) {
    __shared__ float As[BKK][BM + 4];
    __shared__ float Bs[BKK][BN + 4];
    const int b = blockIdx.z;
    const float* Ab = g_nA + (size_t)b * NN * NC;
    const float* Bb = g_nB + (size_t)b * NN * NC;
    float* Cb = C + (size_t)b * NN * NN;
    int tid = threadIdx.x;
    int tx = tid & 15, ty = tid >> 4;
    int m0 = blockIdx.x * BM, n0 = blockIdx.y * BN;
    float acc[8][8];
#pragma unroll
    for (int i = 0; i < 8; i++)
#pragma unroll
        for (int j = 0; j < 8; j++) acc[i][j] = 0.f;

    for (int k0 = 0; k0 < NC; k0 += BKK) {
#pragma unroll
        for (int q = tid; q < 512; q += 256) {
            int row = q >> 2, c4 = (q & 3) * 4;
            float4 va = *(const float4*)&Ab[(size_t)(m0 + row) * NC + k0 + c4];
            As[c4 + 0][row] = va.x; As[c4 + 1][row] = va.y;
            As[c4 + 2][row] = va.z; As[c4 + 3][row] = va.w;
            float4 vb = *(const float4*)&Bb[(size_t)(n0 + row) * NC + k0 + c4];
            Bs[c4 + 0][row] = vb.x; Bs[c4 + 1][row] = vb.y;
            Bs[c4 + 2][row] = vb.z; Bs[c4 + 3][row] = vb.w;
        }
        __syncthreads();
#pragma unroll
        for (int kk = 0; kk < BKK; kk++) {
            float4 a0 = *(const float4*)&As[kk][ty * 8];
            float4 a1 = *(const float4*)&As[kk][ty * 8 + 4];
            float4 b0 = *(const float4*)&Bs[kk][tx * 8];
            float4 b1 = *(const float4*)&Bs[kk][tx * 8 + 4];
            float ar[8] = {a0.x, a0.y, a0.z, a0.w, a1.x, a1.y, a1.z, a1.w};
            float br[8] = {b0.x, b0.y, b0.z, b0.w, b1.x, b1.y, b1.z, b1.w};
#pragma unroll
            for (int i = 0; i < 8; i++)
#pragma unroll
                for (int j = 0; j < 8; j++)
                    acc[i][j] = fmaf(ar[i], br[j], acc[i][j]);
        }
        __syncthreads();
    }
#pragma unroll
    for (int i = 0; i < 8; i++) {
        int m = m0 + ty * 8 + i;
#pragma unroll
        for (int j = 0; j < 8; j += 4) {
            float4 w = make_float4(acc[i][j], acc[i][j + 1], acc[i][j + 2], acc[i][j + 3]);
            *(float4*)&Cb[(size_t)m * NN + n0 + tx * 8 + j] = w;
        }
    }
}

// -------- tiled transpose with x20 scale: g_ST[b][j][i] = 20*sim[b][i][j] --------
__global__ void transpose_scale_kernel(const float* __restrict__ in) {
    __shared__ float tile[32][33];
    int b = blockIdx.z;
    const float* ib = in + (size_t)b * NN * NN;
    float* ob = g_ST + (size_t)b * NN * NN;
    int j0 = blockIdx.x * 32, i0 = blockIdx.y * 32;
    int tx = threadIdx.x, ty = threadIdx.y;   // 32 x 8
#pragma unroll
    for (int r = 0; r < 4; r++) {
        int i = i0 + ty + r * 8;
        tile[ty + r * 8][tx] = 20.f * ib[(size_t)i * NN + j0 + tx];
    }
    __syncthreads();
#pragma unroll
    for (int r = 0; r < 4; r++) {
        int j = j0 + ty + r * 8;
        ob[(size_t)j * NN + i0 + tx] = tile[tx][ty + r * 8];
    }
}

// -------- Sinkhorn u-update: u[r] = log_mu[r] - lse_j( Z[r,j] + v[j] ) --------
__global__ void __launch_bounds__(256) sink_u_kernel(const float* __restrict__ sim) {
    __shared__ float sw[32];
    int r = blockIdx.x, b = blockIdx.y, tid = threadIdx.x;
    const float* vv = g_v + b * (NN + 1);
    const float* srow = sim + (size_t)b * NN * NN + (size_t)r * NN;
    float tv[17];
    float m = -FLT_MAX;
#pragma unroll
    for (int k = 0; k < 17; k++) {
        int j = tid + (k << 8);
        float t = -FLT_MAX;
        if (j <= NN) {
            t = vv[j];
            if (r < NN && j < NN) t = fmaf(20.f, srow[j], t);
        }
        tv[k] = t; m = fmaxf(m, t);
    }
    float M = blockReduceMax(m, sw);
    float s = 0.f;
#pragma unroll
    for (int k = 0; k < 17; k++)
        if (tv[k] > -FLT_MAX) s += expf(tv[k] - M);
    float S = blockReduceSum(s, sw);
    if (tid == 0)
        g_u[b * (NN + 1) + r] = ((r < NN) ? NORMC : LOGMC) - (M + logf(S));
}

// -------- Sinkhorn v-update (uses scaled transposed scores) --------
__global__ void __launch_bounds__(256) sink_v_kernel() {
    __shared__ float sw[32];
    int r = blockIdx.x, b = blockIdx.y, tid = threadIdx.x;
    const float* uu = g_u + b * (NN + 1);
    const float* srow = g_ST + (size_t)b * NN * NN + (size_t)r * NN;
    float tv[17];
    float m = -FLT_MAX;
#pragma unroll
    for (int k = 0; k < 17; k++) {
        int i = tid + (k << 8);
        float t = -FLT_MAX;
        if (i <= NN) {
            t = uu[i];
            if (r < NN && i < NN) t += srow[i];
        }
        tv[k] = t; m = fmaxf(m, t);
    }
    float M = blockReduceMax(m, sw);
    float s = 0.f;
#pragma unroll
    for (int k = 0; k < 17; k++)
        if (tv[k] > -FLT_MAX) s += expf(tv[k] - M);
    float S = blockReduceSum(s, sw);
    if (tid == 0)
        g_v[b * (NN + 1) + r] = ((r < NN) ? NORMC : LOGMC) - (M + logf(S));
}

// -------- per-row: entropy + top-8 (vals, idx, gathered pos_B) --------
__global__ void __launch_bounds__(256) row_final_kernel(const float* __restrict__ sim,
                                                        const float* __restrict__ posB,
                                                        float* __restrict__ ent_out) {
    __shared__ float a[NN];
    __shared__ float sw[32];
    __shared__ int   swi[32];
    __shared__ float s_bv;
    __shared__ int   s_bi;
    int r = blockIdx.x, b = blockIdx.y, tid = threadIdx.x;
    const float* vv = g_v + b * (NN + 1);
    const float* srow = sim + (size_t)b * NN * NN + (size_t)r * NN;
    float ui = g_u[b * (NN + 1) + r];
#pragma unroll
    for (int k = 0; k < 16; k++) {
        int j = tid + (k << 8);
        a[j] = fmaf(20.f, srow[j], vv[j]);
    }
    __syncthreads();
    // row sum of ot
    float s = 0.f;
#pragma unroll
    for (int k = 0; k < 16; k++) s += expf(a[tid + (k << 8)] + ui);
    float S = blockReduceSum(s, sw);
    float inv = 1.f / (S + 1e-8f);
    // entropy
    float e = 0.f;
#pragma unroll
    for (int k = 0; k < 16; k++) {
        float p = expf(a[tid + (k << 8)] + ui) * inv;
        e -= p * logf(p + 1e-8f);
    }
    float E = blockReduceSum(e, sw);
    if (tid == 0) ent_out[b * NN + r] = E;
    // top-8 extraction
    long base = ((long)(b * NN + r)) * NK;
    int wid = tid >> 5, lane = tid & 31;
    for (int t = 0; t < NK; t++) {
        float bv = -FLT_MAX; int bi = 0;
#pragma unroll
        for (int k = 0; k < 16; k++) {
            int j = tid + (k << 8);
            float x = a[j];
            if (x > bv) { bv = x; bi = j; }
        }
#pragma unroll
        for (int o = 16; o; o >>= 1) {
            float ov = __shfl_xor_sync(0xffffffffu, bv, o);
            int   oi = __shfl_xor_sync(0xffffffffu, bi, o);
            if (ov > bv || (ov == bv && oi < bi)) { bv = ov; bi = oi; }
        }
        __syncthreads();
        if (lane == 0) { sw[wid] = bv; swi[wid] = bi; }
        __syncthreads();
        if (wid == 0) {
            float x = (lane < 8) ? sw[lane] : -FLT_MAX;
            int  xi = (lane < 8) ? swi[lane] : 0;
#pragma unroll
            for (int o = 4; o; o >>= 1) {
                float ov = __shfl_xor_sync(0xffffffffu, x, o);
                int   oi = __shfl_xor_sync(0xffffffffu, xi, o);
                if (ov > x || (ov == x && oi < xi)) { x = ov; xi = oi; }
            }
            if (lane == 0) { s_bv = x; s_bi = xi; }
        }
        __syncthreads();
        if (tid == 0) {
            int idx = s_bi;
            g_tki[base + t] = idx;
            g_tkv[base + t] = expf(s_bv + ui);
            float px = posB[((size_t)b * NN + idx) * 2];
            float py = posB[((size_t)b * NN + idx) * 2 + 1];
            g_tkp[(base + t) * 2]     = px;
            g_tkp[(base + t) * 2 + 1] = py;
            a[idx] = -FLT_MAX;
        }
        __syncthreads();
    }
}

// -------- 7x7 local displacement variance -> geometric score --------
__global__ void __launch_bounds__(256) geo_kernel(const float* __restrict__ posA) {
    __shared__ float dx[NN];
    __shared__ float dy[NN];
    int k = blockIdx.x, b = blockIdx.y, tid = threadIdx.x;
    for (int n = tid; n < NN; n += 256) {
        size_t tp = ((size_t)(b * NN + n) * NK + k) * 2;
        size_t pp = ((size_t)b * NN + n) * 2;
        dx[n] = g_tkp[tp]     - posA[pp];
        dy[n] = g_tkp[tp + 1] - posA[pp + 1];
    }
    __syncthreads();
    for (int n = tid; n < NN; n += 256) {
        int h = n >> 6, w = n & 63;
        float s = 0.f; int cnt = 0;
        for (int di = -3; di <= 3; di++) {
            int hh = h + di;
            if ((unsigned)hh >= 64u) continue;
            for (int dj = -3; dj <= 3; dj++) {
                int ww = w + dj;
                if ((unsigned)ww >= 64u) continue;
                int m = hh * 64 + ww;
                s += dx[m] + dy[m];
                cnt += 2;
            }
        }
        float mean = s * (1.f / 98.f);
        float ssd = (float)(98 - cnt) * mean * mean;   // OOB zeros count
        for (int di = -3; di <= 3; di++) {
            int hh = h + di;
            if ((unsigned)hh >= 64u) continue;
            for (int dj = -3; dj <= 3; dj++) {
                int ww = w + dj;
                if ((unsigned)ww >= 64u) continue;
                int m = hh * 64 + ww;
                float ax = dx[m] - mean, ay = dy[m] - mean;
                ssd += ax * ax + ay * ay;
            }
        }
        float var = ssd * (1.f / 97.f);
        g_geo[(size_t)(b * NN + n) * NK + k] = 1.f / (1.f + 100.f * var);
    }
}

// -------- softmax-combine -> refined warp --------
__global__ void combine_kernel(float* __restrict__ outRW) {
    int t = blockIdx.x * blockDim.x + threadIdx.x;
    if (t >= NB * NN) return;
    size_t base = (size_t)t * NK;
    float c[NK]; float m = -FLT_MAX;
#pragma unroll
    for (int k = 0; k < NK; k++) {
        c[k] = g_tkv[base + k] + 1.5f * g_geo[base + k];
        m = fmaxf(m, c[k]);
    }
    float sw = 0.f, rx = 0.f, ry = 0.f;
#pragma unroll
    for (int k = 0; k < NK; k++) {
        float w = expf((c[k] - m) * 20.f);
        sw += w;
        rx += g_tkp[(base + k) * 2]     * w;
        ry += g_tkp[(base + k) * 2 + 1] * w;
    }
    outRW[(size_t)t * 2]     = rx / sw;
    outRW[(size_t)t * 2 + 1] = ry / sw;
}

extern "C" void kernel_launch(void* const* d_in, const int* in_sizes, int n_in,
                              void* d_out, int out_size) {
    const float* fA = (const float*)d_in[0];
    const float* fB = (const float*)d_in[1];
    const float* pA = (const float*)d_in[2];
    const float* pB = (const float*)d_in[3];
    (void)in_sizes; (void)n_in; (void)out_size;

    float* out = (float*)d_out;
    float* out_rw  = out;                       // [2,4096,2]
    float* out_ent = out + NB * NN * 2;         // [2,4096]
    float* out_sim = out + NB * NN * 2 + NB * NN;  // [2,4096,4096]

    zero_uv_kernel<<<(NB * (NN + 1) + 255) / 256, 256>>>();
    normalize_kernel<<<(2 * NB * NN * 32 + 255) / 256, 256>>>(fA, fB);
    gemm_kernel<<<dim3(NN / BM, NN / BN, NB), 256>>>(out_sim);
    transpose_scale_kernel<<<dim3(NN / 32, NN / 32, NB), dim3(32, 8)>>>(out_sim);
    for (int it = 0; it < 5; it++) {
        sink_u_kernel<<<dim3(NN + 1, NB), 256>>>(out_sim);
        sink_v_kernel<<<dim3(NN + 1, NB), 256>>>();
    }
    row_final_kernel<<<dim3(NN, NB), 256>>>(out_sim, pB, out_ent);
    geo_kernel<<<dim3(NK, NB), 256>>>(pA);
    combine_kernel<<<(NB * NN + 255) / 256, 256>>>(out_rw);
}

// round 2
// speedup vs baseline: 1.0313x; 1.0313x over previous
#include <cuda_runtime.h>
#include <math.h>
#include <float.h>

#define NB 2
#define NN 4096
#define NC 128
#define NK 8

#define NORMC  (-9.010913347279289f)   // -log(8192)
#define LOGMC  (-0.6931471805599453f)  // log(4096) - log(8192)

// -------- scratch (static device globals; no allocation) --------
__device__ float g_nA[NB * NN * NC];
__device__ float g_nB[NB * NN * NC];
__device__ float g_ST[(size_t)NB * NN * NN];   // 20 * sim^T  (134 MB)
__device__ float g_u[NB * (NN + 1)];
__device__ float g_v[NB * (NN + 1)];
__device__ float g_part[(size_t)NB * NN * 32]; // per-tile row expsum partials
__device__ float g_tkv[NB * NN * NK];
__device__ int   g_tki[NB * NN * NK];
__device__ float g_tkp[NB * NN * NK * 2];
__device__ float g_geo[NB * NN * NK];

// -------- f32x2 packed helpers --------
__device__ __forceinline__ unsigned long long dup2f(float x) {
    unsigned long long r;
    asm("mov.b64 %0, {%1, %1};" : "=l"(r) : "r"(__float_as_uint(x)));
    return r;
}
__device__ __forceinline__ void ffma2(unsigned long long& d, unsigned long long a,
                                      unsigned long long b) {
    asm("fma.rn.f32x2 %0, %1, %2, %0;" : "+l"(d) : "l"(a), "l"(b));
}
__device__ __forceinline__ float2 unpk2(unsigned long long v) {
    float lo, hi;
    asm("mov.b64 {%0, %1}, %2;" : "=f"(lo), "=f"(hi) : "l"(v));
    return make_float2(lo, hi);
}

// -------- reduction helpers (blockDim == 256) --------
__device__ __forceinline__ float warpMaxF(float v) {
#pragma unroll
    for (int o = 16; o; o >>= 1) v = fmaxf(v, __shfl_xor_sync(0xffffffffu, v, o));
    return v;
}
__device__ __forceinline__ float warpSumF(float v) {
#pragma unroll
    for (int o = 16; o; o >>= 1) v += __shfl_xor_sync(0xffffffffu, v, o);
    return v;
}
__device__ __forceinline__ float blockReduceMax(float v, float* sw) {
    v = warpMaxF(v);
    int wid = threadIdx.x >> 5, lane = threadIdx.x & 31;
    __syncthreads();
    if (lane == 0) sw[wid] = v;
    __syncthreads();
    if (wid == 0) {
        float x = (lane < 8) ? sw[lane] : -FLT_MAX;
        x = warpMaxF(x);
        if (lane == 0) sw[0] = x;
    }
    __syncthreads();
    return sw[0];
}
__device__ __forceinline__ float blockReduceSum(float v, float* sw) {
    v = warpSumF(v);
    int wid = threadIdx.x >> 5, lane = threadIdx.x & 31;
    __syncthreads();
    if (lane == 0) sw[wid] = v;
    __syncthreads();
    if (wid == 0) {
        float x = (lane < 8) ? sw[lane] : 0.f;
        x = warpSumF(x);
        if (lane == 0) sw[0] = x;
    }
    __syncthreads();
    return sw[0];
}

// -------- row L2 normalize (warp per row; rows 0..8191=A, 8192..16383=B) --------
__global__ void __launch_bounds__(256) normalize_kernel(const float* __restrict__ fA,
                                                        const float* __restrict__ fB) {
    int gw = (blockIdx.x * blockDim.x + threadIdx.x) >> 5;
    int lane = threadIdx.x & 31;
    if (gw >= 2 * NB * NN) return;
    int row = gw & (NB * NN - 1);
    const float* src = (gw < NB * NN) ? fA : fB;
    float* dst = (gw < NB * NN) ? g_nA : g_nB;
    const float* p = src + (size_t)row * NC;
    float x[4]; float ss = 0.f;
#pragma unroll
    for (int l = 0; l < 4; l++) { x[l] = p[lane + l * 32]; ss += x[l] * x[l]; }
    ss = warpSumF(ss);
    float sc = 1.f / fmaxf(sqrtf(ss), 1e-12f);
    float* q = dst + (size_t)row * NC;
#pragma unroll
    for (int l = 0; l < 4; l++) q[lane + l * 32] = x[l] * sc;
}

// -------- f32x2 GEMM + fused transpose-scale + fused first-u partials --------
#define BM 128
#define BN 128
#define BKK 16
#define BNS 192   // skewed B width: col + (col>>3)*4, max 187

__global__ void __launch_bounds__(256) gemm_kernel(float* __restrict__ C) {
    __shared__ unsigned long long As2[BKK][BM];   // 16KB, each value duplicated (x,x)
    __shared__ float Bs[BKK][BNS];                // 12KB, 4-word skew per 8 cols
    const int b = blockIdx.z;
    const float* Ab = g_nA + (size_t)b * NN * NC;
    const float* Bb = g_nB + (size_t)b * NN * NC;
    float* Cb = C + (size_t)b * NN * NN;
    float* STb = g_ST + (size_t)b * NN * NN;
    int tid = threadIdx.x;
    int tx = tid & 15, ty = tid >> 4;
    int m0 = blockIdx.x * BM, n0 = blockIdx.y * BN;

    unsigned long long acc[8][4];
#pragma unroll
    for (int i = 0; i < 8; i++)
#pragma unroll
        for (int p = 0; p < 4; p++) acc[i][p] = 0ull;

    for (int k0 = 0; k0 < NC; k0 += BKK) {
#pragma unroll
        for (int q = tid; q < 512; q += 256) {
            int row = q >> 2, c4 = (q & 3) * 4;
            float4 va = *(const float4*)&Ab[(size_t)(m0 + row) * NC + k0 + c4];
            As2[c4 + 0][row] = dup2f(va.x); As2[c4 + 1][row] = dup2f(va.y);
            As2[c4 + 2][row] = dup2f(va.z); As2[c4 + 3][row] = dup2f(va.w);
            float4 vb = *(const float4*)&Bb[(size_t)(n0 + row) * NC + k0 + c4];
            int rs = row + ((row >> 3) << 2);
            Bs[c4 + 0][rs] = vb.x; Bs[c4 + 1][rs] = vb.y;
            Bs[c4 + 2][rs] = vb.z; Bs[c4 + 3][rs] = vb.w;
        }
        __syncthreads();
#pragma unroll
        for (int kk = 0; kk < BKK; kk++) {
            ulonglong2 a01 = *(const ulonglong2*)&As2[kk][ty * 8 + 0];
            ulonglong2 a23 = *(const ulonglong2*)&As2[kk][ty * 8 + 2];
            ulonglong2 a45 = *(const ulonglong2*)&As2[kk][ty * 8 + 4];
            ulonglong2 a67 = *(const ulonglong2*)&As2[kk][ty * 8 + 6];
            ulonglong2 b03 = *(const ulonglong2*)&Bs[kk][tx * 12 + 0];
            ulonglong2 b47 = *(const ulonglong2*)&Bs[kk][tx * 12 + 4];
            unsigned long long av[8] = {a01.x, a01.y, a23.x, a23.y,
                                        a45.x, a45.y, a67.x, a67.y};
            unsigned long long bv[4] = {b03.x, b03.y, b47.x, b47.y};
#pragma unroll
            for (int i = 0; i < 8; i++)
#pragma unroll
                for (int p = 0; p < 4; p++) ffma2(acc[i][p], av[i], bv[p]);
        }
        __syncthreads();
    }

    // unpack
    float c[8][8];
#pragma unroll
    for (int i = 0; i < 8; i++)
#pragma unroll
        for (int p = 0; p < 4; p++) {
            float2 f = unpk2(acc[i][p]);
            c[i][2 * p] = f.x; c[i][2 * p + 1] = f.y;
        }
    // sim store
#pragma unroll
    for (int i = 0; i < 8; i++) {
        size_t ro = (size_t)(m0 + ty * 8 + i) * NN + n0 + tx * 8;
        *(float4*)&Cb[ro]     = make_float4(c[i][0], c[i][1], c[i][2], c[i][3]);
        *(float4*)&Cb[ro + 4] = make_float4(c[i][4], c[i][5], c[i][6], c[i][7]);
    }
    // 20*sim^T store
#pragma unroll
    for (int j = 0; j < 8; j++) {
        size_t ro = (size_t)(n0 + tx * 8 + j) * NN + m0 + ty * 8;
        *(float4*)&STb[ro] = make_float4(20.f * c[0][j], 20.f * c[1][j],
                                         20.f * c[2][j], 20.f * c[3][j]);
        *(float4*)&STb[ro + 4] = make_float4(20.f * c[4][j], 20.f * c[5][j],
                                             20.f * c[6][j], 20.f * c[7][j]);
    }
    // first-u partials: sum_j exp(20*c - 20) per row, reduced over the 16 tx lanes
#pragma unroll
    for (int i = 0; i < 8; i++) {
        float s = 0.f;
#pragma unroll
        for (int j = 0; j < 8; j++) s += __expf(fmaf(20.f, c[i][j], -20.f));
#pragma unroll
        for (int o = 1; o < 16; o <<= 1) s += __shfl_xor_sync(0xffffffffu, s, o);
        if (tx == 0)
            g_part[((size_t)(b * NN + m0 + ty * 8 + i)) * 32 + blockIdx.y] = s;
    }
}

// -------- finalize fused first u-update --------
__global__ void finalize_u_kernel() {
    int t = blockIdx.x * blockDim.x + threadIdx.x;
    if (t >= NB * (NN + 1)) return;
    int b = t / (NN + 1), r = t % (NN + 1);
    float u;
    if (r < NN) {
        const float* p = g_part + ((size_t)(b * NN + r)) * 32;
        float s = __expf(-20.f);   // dustbin column j=N: exp(0 + v[N]=0 - 20)
#pragma unroll
        for (int k = 0; k < 32; k++) s += p[k];
        u = NORMC - (20.f + __logf(s));
    } else {
        u = LOGMC - __logf((float)(NN + 1));
    }
    g_u[b * (NN + 1) + r] = u;
}

// -------- Sinkhorn u-update: u[r] = log_mu[r] - lse_j( Z[r,j] + v[j] ) --------
__global__ void __launch_bounds__(256) sink_u_kernel(const float* __restrict__ sim) {
    __shared__ float sw[32];
    int r = blockIdx.x, b = blockIdx.y, tid = threadIdx.x;
    const float* vv = g_v + b * (NN + 1);
    const float* srow = sim + (size_t)b * NN * NN + (size_t)r * NN;
    float tv[17];
    float m = -FLT_MAX;
#pragma unroll
    for (int k = 0; k < 17; k++) {
        int j = tid + (k << 8);
        float t = -FLT_MAX;
        if (j <= NN) {
            t = vv[j];
            if (r < NN && j < NN) t = fmaf(20.f, srow[j], t);
        }
        tv[k] = t; m = fmaxf(m, t);
    }
    float M = blockReduceMax(m, sw);
    float s = 0.f;
#pragma unroll
    for (int k = 0; k < 17; k++)
        if (tv[k] > -FLT_MAX) s += __expf(tv[k] - M);
    float S = blockReduceSum(s, sw);
    if (tid == 0)
        g_u[b * (NN + 1) + r] = ((r < NN) ? NORMC : LOGMC) - (M + __logf(S));
}

// -------- Sinkhorn v-update (uses scaled transposed scores) --------
__global__ void __launch_bounds__(256) sink_v_kernel() {
    __shared__ float sw[32];
    int r = blockIdx.x, b = blockIdx.y, tid = threadIdx.x;
    const float* uu = g_u + b * (NN + 1);
    const float* srow = g_ST + (size_t)b * NN * NN + (size_t)r * NN;
    float tv[17];
    float m = -FLT_MAX;
#pragma unroll
    for (int k = 0; k < 17; k++) {
        int i = tid + (k << 8);
        float t = -FLT_MAX;
        if (i <= NN) {
            t = uu[i];
            if (r < NN && i < NN) t += srow[i];
        }
        tv[k] = t; m = fmaxf(m, t);
    }
    float M = blockReduceMax(m, sw);
    float s = 0.f;
#pragma unroll
    for (int k = 0; k < 17; k++)
        if (tv[k] > -FLT_MAX) s += __expf(tv[k] - M);
    float S = blockReduceSum(s, sw);
    if (tid == 0)
        g_v[b * (NN + 1) + r] = ((r < NN) ? NORMC : LOGMC) - (M + __logf(S));
}

// -------- per-row: entropy + top-8 (vals, idx, gathered pos_B) --------
__global__ void __launch_bounds__(256) row_final_kernel(const float* __restrict__ sim,
                                                        const float* __restrict__ posB,
                                                        float* __restrict__ ent_out) {
    __shared__ float a[NN];
    __shared__ float sw[32];
    __shared__ int   swi[32];
    __shared__ float s_bv;
    __shared__ int   s_bi;
    int r = blockIdx.x, b = blockIdx.y, tid = threadIdx.x;
    const float* vv = g_v + b * (NN + 1);
    const float* srow = sim + (size_t)b * NN * NN + (size_t)r * NN;
    float ui = g_u[b * (NN + 1) + r];
#pragma unroll
    for (int k = 0; k < 16; k++) {
        int j = tid + (k << 8);
        a[j] = fmaf(20.f, srow[j], vv[j]);
    }
    __syncthreads();
    // row sum of ot
    float s = 0.f;
#pragma unroll
    for (int k = 0; k < 16; k++) s += __expf(a[tid + (k << 8)] + ui);
    float S = blockReduceSum(s, sw);
    float inv = 1.f / (S + 1e-8f);
    // entropy
    float e = 0.f;
#pragma unroll
    for (int k = 0; k < 16; k++) {
        float p = __expf(a[tid + (k << 8)] + ui) * inv;
        e -= p * __logf(p + 1e-8f);
    }
    float E = blockReduceSum(e, sw);
    if (tid == 0) ent_out[b * NN + r] = E;
    // top-8 extraction
    long base = ((long)(b * NN + r)) * NK;
    int wid = tid >> 5, lane = tid & 31;
    for (int t = 0; t < NK; t++) {
        float bv = -FLT_MAX; int bi = 0;
#pragma unroll
        for (int k = 0; k < 16; k++) {
            int j = tid + (k << 8);
            float x = a[j];
            if (x > bv) { bv = x; bi = j; }
        }
#pragma unroll
        for (int o = 16; o; o >>= 1) {
            float ov = __shfl_xor_sync(0xffffffffu, bv, o);
            int   oi = __shfl_xor_sync(0xffffffffu, bi, o);
            if (ov > bv || (ov == bv && oi < bi)) { bv = ov; bi = oi; }
        }
        __syncthreads();
        if (lane == 0) { sw[wid] = bv; swi[wid] = bi; }
        __syncthreads();
        if (wid == 0) {
            float x = (lane < 8) ? sw[lane] : -FLT_MAX;
            int  xi = (lane < 8) ? swi[lane] : 0;
#pragma unroll
            for (int o = 4; o; o >>= 1) {
                float ov = __shfl_xor_sync(0xffffffffu, x, o);
                int   oi = __shfl_xor_sync(0xffffffffu, xi, o);
                if (ov > x || (ov == x && oi < xi)) { x = ov; xi = oi; }
            }
            if (lane == 0) { s_bv = x; s_bi = xi; }
        }
        __syncthreads();
        if (tid == 0) {
            int idx = s_bi;
            g_tki[base + t] = idx;
            g_tkv[base + t] = expf(s_bv + ui);
            float px = posB[((size_t)b * NN + idx) * 2];
            float py = posB[((size_t)b * NN + idx) * 2 + 1];
            g_tkp[(base + t) * 2]     = px;
            g_tkp[(base + t) * 2 + 1] = py;
            a[idx] = -FLT_MAX;
        }
        __syncthreads();
    }
}

// -------- 7x7 local displacement variance -> geometric score --------
__global__ void __launch_bounds__(256) geo_kernel(const float* __restrict__ posA) {
    __shared__ float dx[NN];
    __shared__ float dy[NN];
    int k = blockIdx.x, b = blockIdx.y, tid = threadIdx.x;
    for (int n = tid; n < NN; n += 256) {
        size_t tp = ((size_t)(b * NN + n) * NK + k) * 2;
        size_t pp = ((size_t)b * NN + n) * 2;
        dx[n] = g_tkp[tp]     - posA[pp];
        dy[n] = g_tkp[tp + 1] - posA[pp + 1];
    }
    __syncthreads();
    for (int n = tid; n < NN; n += 256) {
        int h = n >> 6, w = n & 63;
        float s = 0.f; int cnt = 0;
        for (int di = -3; di <= 3; di++) {
            int hh = h + di;
            if ((unsigned)hh >= 64u) continue;
            for (int dj = -3; dj <= 3; dj++) {
                int ww = w + dj;
                if ((unsigned)ww >= 64u) continue;
                int m = hh * 64 + ww;
                s += dx[m] + dy[m];
                cnt += 2;
            }
        }
        float mean = s * (1.f / 98.f);
        float ssd = (float)(98 - cnt) * mean * mean;   // OOB zeros count
        for (int di = -3; di <= 3; di++) {
            int hh = h + di;
            if ((unsigned)hh >= 64u) continue;
            for (int dj = -3; dj <= 3; dj++) {
                int ww = w + dj;
                if ((unsigned)ww >= 64u) continue;
                int m = hh * 64 + ww;
                float ax = dx[m] - mean, ay = dy[m] - mean;
                ssd += ax * ax + ay * ay;
            }
        }
        float var = ssd * (1.f / 97.f);
        g_geo[(size_t)(b * NN + n) * NK + k] = 1.f / (1.f + 100.f * var);
    }
}

// -------- softmax-combine -> refined warp --------
__global__ void combine_kernel(float* __restrict__ outRW) {
    int t = blockIdx.x * blockDim.x + threadIdx.x;
    if (t >= NB * NN) return;
    size_t base = (size_t)t * NK;
    float c[NK]; float m = -FLT_MAX;
#pragma unroll
    for (int k = 0; k < NK; k++) {
        c[k] = g_tkv[base + k] + 1.5f * g_geo[base + k];
        m = fmaxf(m, c[k]);
    }
    float sw = 0.f, rx = 0.f, ry = 0.f;
#pragma unroll
    for (int k = 0; k < NK; k++) {
        float w = expf((c[k] - m) * 20.f);
        sw += w;
        rx += g_tkp[(base + k) * 2]     * w;
        ry += g_tkp[(base + k) * 2 + 1] * w;
    }
    outRW[(size_t)t * 2]     = rx / sw;
    outRW[(size_t)t * 2 + 1] = ry / sw;
}

extern "C" void kernel_launch(void* const* d_in, const int* in_sizes, int n_in,
                              void* d_out, int out_size) {
    const float* fA = (const float*)d_in[0];
    const float* fB = (const float*)d_in[1];
    const float* pA = (const float*)d_in[2];
    const float* pB = (const float*)d_in[3];
    (void)in_sizes; (void)n_in; (void)out_size;

    float* out = (float*)d_out;
    float* out_rw  = out;                          // [2,4096,2]
    float* out_ent = out + NB * NN * 2;            // [2,4096]
    float* out_sim = out + NB * NN * 2 + NB * NN;  // [2,4096,4096]

    normalize_kernel<<<(2 * NB * NN * 32 + 255) / 256, 256>>>(fA, fB);
    gemm_kernel<<<dim3(NN / BM, NN / BN, NB), 256>>>(out_sim);
    finalize_u_kernel<<<(NB * (NN + 1) + 255) / 256, 256>>>();
    // u1 fused above; remaining passes: v1, (u,v) x4
    sink_v_kernel<<<dim3(NN + 1, NB), 256>>>();
    for (int it = 0; it < 4; it++) {
        sink_u_kernel<<<dim3(NN + 1, NB), 256>>>(out_sim);
        sink_v_kernel<<<dim3(NN + 1, NB), 256>>>();
    }
    row_final_kernel<<<dim3(NN, NB), 256>>>(out_sim, pB, out_ent);
    geo_kernel<<<dim3(NK, NB), 256>>>(pA);
    combine_kernel<<<(NB * NN + 255) / 256, 256>>>(out_rw);
}

// round 3
// speedup vs baseline: 1.2725x; 1.2339x over previous
#include <cuda_runtime.h>
#include <math.h>
#include <float.h>

#define NB 2
#define NN 4096
#define NC 128
#define NK 8
#define UVS 4100   // padded stride for u/v so each batch slice is 16B-aligned

#define NORMC  (-9.010913347279289f)   // -log(8192)
#define LOGMC  (-0.6931471805599453f)  // log(4096) - log(8192)

// -------- scratch (static device globals; no allocation) --------
__device__ float g_nA[NB * NN * NC];
__device__ float g_nB[NB * NN * NC];
__device__ float g_ST[(size_t)NB * NN * NN];   // 20 * sim^T  (134 MB)
__device__ float g_u[NB * UVS];
__device__ float g_v[NB * UVS];
__device__ float g_part[(size_t)NB * NN * 32]; // per-tile row expsum partials
__device__ float g_tkv[NB * NN * NK];
__device__ float g_tkp[NB * NN * NK * 2];
__device__ float g_geo[NB * NN * NK];

// -------- f32x2 packed helpers --------
__device__ __forceinline__ unsigned long long dup2f(float x) {
    unsigned long long r;
    asm("mov.b64 %0, {%1, %1};" : "=l"(r) : "r"(__float_as_uint(x)));
    return r;
}
__device__ __forceinline__ void ffma2(unsigned long long& d, unsigned long long a,
                                      unsigned long long b) {
    asm("fma.rn.f32x2 %0, %1, %2, %0;" : "+l"(d) : "l"(a), "l"(b));
}
__device__ __forceinline__ float2 unpk2(unsigned long long v) {
    float lo, hi;
    asm("mov.b64 {%0, %1}, %2;" : "=f"(lo), "=f"(hi) : "l"(v));
    return make_float2(lo, hi);
}

// -------- reduction helpers (blockDim == 256) --------
__device__ __forceinline__ float warpMaxF(float v) {
#pragma unroll
    for (int o = 16; o; o >>= 1) v = fmaxf(v, __shfl_xor_sync(0xffffffffu, v, o));
    return v;
}
__device__ __forceinline__ float warpSumF(float v) {
#pragma unroll
    for (int o = 16; o; o >>= 1) v += __shfl_xor_sync(0xffffffffu, v, o);
    return v;
}
__device__ __forceinline__ float blockReduceMax(float v, float* sw) {
    v = warpMaxF(v);
    int wid = threadIdx.x >> 5, lane = threadIdx.x & 31;
    __syncthreads();
    if (lane == 0) sw[wid] = v;
    __syncthreads();
    if (wid == 0) {
        float x = (lane < 8) ? sw[lane] : -FLT_MAX;
        x = warpMaxF(x);
        if (lane == 0) sw[0] = x;
    }
    __syncthreads();
    return sw[0];
}
__device__ __forceinline__ float blockReduceSum(float v, float* sw) {
    v = warpSumF(v);
    int wid = threadIdx.x >> 5, lane = threadIdx.x & 31;
    __syncthreads();
    if (lane == 0) sw[wid] = v;
    __syncthreads();
    if (wid == 0) {
        float x = (lane < 8) ? sw[lane] : 0.f;
        x = warpSumF(x);
        if (lane == 0) sw[0] = x;
    }
    __syncthreads();
    return sw[0];
}

// -------- row L2 normalize --------
__global__ void __launch_bounds__(256) normalize_kernel(const float* __restrict__ fA,
                                                        const float* __restrict__ fB) {
    int gw = (blockIdx.x * blockDim.x + threadIdx.x) >> 5;
    int lane = threadIdx.x & 31;
    if (gw >= 2 * NB * NN) return;
    int row = gw & (NB * NN - 1);
    const float* src = (gw < NB * NN) ? fA : fB;
    float* dst = (gw < NB * NN) ? g_nA : g_nB;
    const float* p = src + (size_t)row * NC;
    float x[4]; float ss = 0.f;
#pragma unroll
    for (int l = 0; l < 4; l++) { x[l] = p[lane + l * 32]; ss += x[l] * x[l]; }
    ss = warpSumF(ss);
    float sc = 1.f / fmaxf(sqrtf(ss), 1e-12f);
    float* q = dst + (size_t)row * NC;
#pragma unroll
    for (int l = 0; l < 4; l++) q[lane + l * 32] = x[l] * sc;
}

// -------- f32x2 GEMM + fused transpose-scale + fused first-u partials --------
#define BM 128
#define BN 128
#define BKK 16
#define BNS 192

__global__ void __launch_bounds__(256) gemm_kernel(float* __restrict__ C) {
    __shared__ unsigned long long As2[BKK][BM];
    __shared__ float Bs[BKK][BNS];
    __shared__ float stg[16][132];   // 8.25KB transpose staging
    const int b = blockIdx.z;
    const float* Ab = g_nA + (size_t)b * NN * NC;
    const float* Bb = g_nB + (size_t)b * NN * NC;
    float* Cb = C + (size_t)b * NN * NN;
    float* STb = g_ST + (size_t)b * NN * NN;
    int tid = threadIdx.x;
    int tx = tid & 15, ty = tid >> 4;
    int m0 = blockIdx.x * BM, n0 = blockIdx.y * BN;

    unsigned long long acc[8][4];
#pragma unroll
    for (int i = 0; i < 8; i++)
#pragma unroll
        for (int p = 0; p < 4; p++) acc[i][p] = 0ull;

    for (int k0 = 0; k0 < NC; k0 += BKK) {
#pragma unroll
        for (int q = tid; q < 512; q += 256) {
            int row = q >> 2, c4 = (q & 3) * 4;
            float4 va = *(const float4*)&Ab[(size_t)(m0 + row) * NC + k0 + c4];
            As2[c4 + 0][row] = dup2f(va.x); As2[c4 + 1][row] = dup2f(va.y);
            As2[c4 + 2][row] = dup2f(va.z); As2[c4 + 3][row] = dup2f(va.w);
            float4 vb = *(const float4*)&Bb[(size_t)(n0 + row) * NC + k0 + c4];
            int rs = row + ((row >> 3) << 2);
            Bs[c4 + 0][rs] = vb.x; Bs[c4 + 1][rs] = vb.y;
            Bs[c4 + 2][rs] = vb.z; Bs[c4 + 3][rs] = vb.w;
        }
        __syncthreads();
#pragma unroll
        for (int kk = 0; kk < BKK; kk++) {
            ulonglong2 a01 = *(const ulonglong2*)&As2[kk][ty * 8 + 0];
            ulonglong2 a23 = *(const ulonglong2*)&As2[kk][ty * 8 + 2];
            ulonglong2 a45 = *(const ulonglong2*)&As2[kk][ty * 8 + 4];
            ulonglong2 a67 = *(const ulonglong2*)&As2[kk][ty * 8 + 6];
            ulonglong2 b03 = *(const ulonglong2*)&Bs[kk][tx * 12 + 0];
            ulonglong2 b47 = *(const ulonglong2*)&Bs[kk][tx * 12 + 4];
            unsigned long long av[8] = {a01.x, a01.y, a23.x, a23.y,
                                        a45.x, a45.y, a67.x, a67.y};
            unsigned long long bv[4] = {b03.x, b03.y, b47.x, b47.y};
#pragma unroll
            for (int i = 0; i < 8; i++)
#pragma unroll
                for (int p = 0; p < 4; p++) ffma2(acc[i][p], av[i], bv[p]);
        }
        __syncthreads();
    }

    float c[8][8];
#pragma unroll
    for (int i = 0; i < 8; i++)
#pragma unroll
        for (int p = 0; p < 4; p++) {
            float2 f = unpk2(acc[i][p]);
            c[i][2 * p] = f.x; c[i][2 * p + 1] = f.y;
        }
    // sim store (coalesced)
#pragma unroll
    for (int i = 0; i < 8; i++) {
        size_t ro = (size_t)(m0 + ty * 8 + i) * NN + n0 + tx * 8;
        *(float4*)&Cb[ro]     = make_float4(c[i][0], c[i][1], c[i][2], c[i][3]);
        *(float4*)&Cb[ro + 4] = make_float4(c[i][4], c[i][5], c[i][6], c[i][7]);
    }
    // 20*sim^T store via smem staging (coalesced full-line writes)
#pragma unroll
    for (int j = 0; j < 8; j++) {
        __syncthreads();
#pragma unroll
        for (int i = 0; i < 8; i++) stg[tx][ty * 8 + i] = 20.f * c[i][j];
        __syncthreads();
#pragma unroll
        for (int q = tid; q < 512; q += 256) {
            int row = q >> 5, c4 = (q & 31) * 4;
            float4 w = *(float4*)&stg[row][c4];
            *(float4*)&STb[(size_t)(n0 + row * 8 + j) * NN + m0 + c4] = w;
        }
    }
    // first-u partials: sum_j exp(20*c - 20) per row
#pragma unroll
    for (int i = 0; i < 8; i++) {
        float s = 0.f;
#pragma unroll
        for (int j = 0; j < 8; j++) s += __expf(fmaf(20.f, c[i][j], -20.f));
#pragma unroll
        for (int o = 1; o < 16; o <<= 1) s += __shfl_xor_sync(0xffffffffu, s, o);
        if (tx == 0)
            g_part[((size_t)(b * NN + m0 + ty * 8 + i)) * 32 + blockIdx.y] = s;
    }
}

// -------- finalize fused first u-update --------
__global__ void finalize_u_kernel() {
    int t = blockIdx.x * blockDim.x + threadIdx.x;
    if (t >= NB * (NN + 1)) return;
    int b = t / (NN + 1), r = t % (NN + 1);
    float u;
    if (r < NN) {
        const float* p = g_part + ((size_t)(b * NN + r)) * 32;
        float s = __expf(-20.f);   // dustbin column: exp(0 + v=0 - 20)
#pragma unroll
        for (int k = 0; k < 32; k++) s += p[k];
        u = NORMC - (20.f + __logf(s));
    } else {
        u = LOGMC - __logf((float)(NN + 1));
    }
    g_u[b * UVS + r] = u;
}

// -------- Sinkhorn u-update (vectorized): u[r] = log_mu[r] - lse_j(Z[r,j]+v[j]) --------
__global__ void __launch_bounds__(256) sink_u_kernel(const float* __restrict__ sim) {
    __shared__ float sw[32];
    int r = blockIdx.x, b = blockIdx.y, tid = threadIdx.x;
    const float* vv = g_v + b * UVS;
    const float4* vv4 = (const float4*)vv;
    float4 tv[4];
    float m = -FLT_MAX;
    if (r < NN) {
        const float4* s4 = (const float4*)(sim + (size_t)b * NN * NN + (size_t)r * NN);
#pragma unroll
        for (int k = 0; k < 4; k++) {
            int idx = tid + (k << 8);
            float4 s = s4[idx], v = vv4[idx];
            tv[k].x = fmaf(20.f, s.x, v.x); tv[k].y = fmaf(20.f, s.y, v.y);
            tv[k].z = fmaf(20.f, s.z, v.z); tv[k].w = fmaf(20.f, s.w, v.w);
            m = fmaxf(m, fmaxf(fmaxf(tv[k].x, tv[k].y), fmaxf(tv[k].z, tv[k].w)));
        }
    } else {
#pragma unroll
        for (int k = 0; k < 4; k++) {
            tv[k] = vv4[tid + (k << 8)];
            m = fmaxf(m, fmaxf(fmaxf(tv[k].x, tv[k].y), fmaxf(tv[k].z, tv[k].w)));
        }
    }
    float extra = (tid == 0) ? vv[NN] : -FLT_MAX;   // j = NN dustbin (Z=0)
    m = fmaxf(m, extra);
    float M = blockReduceMax(m, sw);
    float s = 0.f;
#pragma unroll
    for (int k = 0; k < 4; k++)
        s += __expf(tv[k].x - M) + __expf(tv[k].y - M)
           + __expf(tv[k].z - M) + __expf(tv[k].w - M);
    if (tid == 0) s += __expf(extra - M);
    float S = blockReduceSum(s, sw);
    if (tid == 0)
        g_u[b * UVS + r] = ((r < NN) ? NORMC : LOGMC) - (M + __logf(S));
}

// -------- Sinkhorn v-update (vectorized; ST already holds 20*sim^T) --------
__global__ void __launch_bounds__(256) sink_v_kernel() {
    __shared__ float sw[32];
    int r = blockIdx.x, b = blockIdx.y, tid = threadIdx.x;
    const float* uu = g_u + b * UVS;
    const float4* uu4 = (const float4*)uu;
    float4 tv[4];
    float m = -FLT_MAX;
    if (r < NN) {
        const float4* s4 = (const float4*)(g_ST + (size_t)b * NN * NN + (size_t)r * NN);
#pragma unroll
        for (int k = 0; k < 4; k++) {
            int idx = tid + (k << 8);
            float4 s = s4[idx], u = uu4[idx];
            tv[k].x = s.x + u.x; tv[k].y = s.y + u.y;
            tv[k].z = s.z + u.z; tv[k].w = s.w + u.w;
            m = fmaxf(m, fmaxf(fmaxf(tv[k].x, tv[k].y), fmaxf(tv[k].z, tv[k].w)));
        }
    } else {
#pragma unroll
        for (int k = 0; k < 4; k++) {
            tv[k] = uu4[tid + (k << 8)];
            m = fmaxf(m, fmaxf(fmaxf(tv[k].x, tv[k].y), fmaxf(tv[k].z, tv[k].w)));
        }
    }
    float extra = (tid == 0) ? uu[NN] : -FLT_MAX;   // i = NN dustbin
    m = fmaxf(m, extra);
    float M = blockReduceMax(m, sw);
    float s = 0.f;
#pragma unroll
    for (int k = 0; k < 4; k++)
        s += __expf(tv[k].x - M) + __expf(tv[k].y - M)
           + __expf(tv[k].z - M) + __expf(tv[k].w - M);
    if (tid == 0) s += __expf(extra - M);
    float S = blockReduceSum(s, sw);
    if (tid == 0)
        g_v[b * UVS + r] = ((r < NN) ? NORMC : LOGMC) - (M + __logf(S));
}

// -------- per-row: entropy + top-8 --------
__global__ void __launch_bounds__(256) row_final_kernel(const float* __restrict__ sim,
                                                        const float* __restrict__ posB,
                                                        float* __restrict__ ent_out) {
    __shared__ float a[NN];
    __shared__ float sw[32];
    __shared__ int   swi[32];
    __shared__ float s_bv;
    __shared__ int   s_bi;
    int r = blockIdx.x, b = blockIdx.y, tid = threadIdx.x;
    const float4* vv4 = (const float4*)(g_v + b * UVS);
    const float4* s4 = (const float4*)(sim + (size_t)b * NN * NN + (size_t)r * NN);
    float ui = g_u[b * UVS + r];
    float4 tv[4];
#pragma unroll
    for (int k = 0; k < 4; k++) {
        int idx = tid + (k << 8);
        float4 s = s4[idx], v = vv4[idx];
        tv[k].x = fmaf(20.f, s.x, v.x); tv[k].y = fmaf(20.f, s.y, v.y);
        tv[k].z = fmaf(20.f, s.z, v.z); tv[k].w = fmaf(20.f, s.w, v.w);
        ((float4*)a)[idx] = tv[k];
    }
    // row sum + entropy from registers
    float s = 0.f, e = 0.f;
#pragma unroll
    for (int k = 0; k < 4; k++) {
        float p;
        p = __expf(tv[k].x + ui); s += p;
        p = __expf(tv[k].y + ui); s += p;
        p = __expf(tv[k].z + ui); s += p;
        p = __expf(tv[k].w + ui); s += p;
    }
    float S = blockReduceSum(s, sw);
    float inv = 1.f / (S + 1e-8f);
#pragma unroll
    for (int k = 0; k < 4; k++) {
        float p;
        p = __expf(tv[k].x + ui) * inv; e -= p * __logf(p + 1e-8f);
        p = __expf(tv[k].y + ui) * inv; e -= p * __logf(p + 1e-8f);
        p = __expf(tv[k].z + ui) * inv; e -= p * __logf(p + 1e-8f);
        p = __expf(tv[k].w + ui) * inv; e -= p * __logf(p + 1e-8f);
    }
    float E = blockReduceSum(e, sw);
    if (tid == 0) ent_out[b * NN + r] = E;
    __syncthreads();
    // top-8 extraction
    long base = ((long)(b * NN + r)) * NK;
    int wid = tid >> 5, lane = tid & 31;
    for (int t = 0; t < NK; t++) {
        float bv = -FLT_MAX; int bi = 0;
#pragma unroll
        for (int k = 0; k < 16; k++) {
            int j = tid + (k << 8);
            float x = a[j];
            if (x > bv) { bv = x; bi = j; }
        }
#pragma unroll
        for (int o = 16; o; o >>= 1) {
            float ov = __shfl_xor_sync(0xffffffffu, bv, o);
            int   oi = __shfl_xor_sync(0xffffffffu, bi, o);
            if (ov > bv || (ov == bv && oi < bi)) { bv = ov; bi = oi; }
        }
        __syncthreads();
        if (lane == 0) { sw[wid] = bv; swi[wid] = bi; }
        __syncthreads();
        if (wid == 0) {
            float x = (lane < 8) ? sw[lane] : -FLT_MAX;
            int  xi = (lane < 8) ? swi[lane] : 0;
#pragma unroll
            for (int o = 4; o; o >>= 1) {
                float ov = __shfl_xor_sync(0xffffffffu, x, o);
                int   oi = __shfl_xor_sync(0xffffffffu, xi, o);
                if (ov > x || (ov == x && oi < xi)) { x = ov; xi = oi; }
            }
            if (lane == 0) { s_bv = x; s_bi = xi; }
        }
        __syncthreads();
        if (tid == 0) {
            int idx = s_bi;
            g_tkv[base + t] = expf(s_bv + ui);
            float px = posB[((size_t)b * NN + idx) * 2];
            float py = posB[((size_t)b * NN + idx) * 2 + 1];
            g_tkp[(base + t) * 2]     = px;
            g_tkp[(base + t) * 2 + 1] = py;
            a[idx] = -FLT_MAX;
        }
        __syncthreads();
    }
}

// -------- 7x7 local displacement variance -> geometric score --------
__global__ void __launch_bounds__(256) geo_kernel(const float* __restrict__ posA) {
    __shared__ float dx[NN];
    __shared__ float dy[NN];
    int k = blockIdx.x, b = blockIdx.y, tid = threadIdx.x;
    for (int n = tid; n < NN; n += 256) {
        size_t tp = ((size_t)(b * NN + n) * NK + k) * 2;
        size_t pp = ((size_t)b * NN + n) * 2;
        dx[n] = g_tkp[tp]     - posA[pp];
        dy[n] = g_tkp[tp + 1] - posA[pp + 1];
    }
    __syncthreads();
    for (int n = tid; n < NN; n += 256) {
        int h = n >> 6, w = n & 63;
        float s = 0.f; int cnt = 0;
        for (int di = -3; di <= 3; di++) {
            int hh = h + di;
            if ((unsigned)hh >= 64u) continue;
            for (int dj = -3; dj <= 3; dj++) {
                int ww = w + dj;
                if ((unsigned)ww >= 64u) continue;
                int m = hh * 64 + ww;
                s += dx[m] + dy[m];
                cnt += 2;
            }
        }
        float mean = s * (1.f / 98.f);
        float ssd = (float)(98 - cnt) * mean * mean;
        for (int di = -3; di <= 3; di++) {
            int hh = h + di;
            if ((unsigned)hh >= 64u) continue;
            for (int dj = -3; dj <= 3; dj++) {
                int ww = w + dj;
                if ((unsigned)ww >= 64u) continue;
                int m = hh * 64 + ww;
                float ax = dx[m] - mean, ay = dy[m] - mean;
                ssd += ax * ax + ay * ay;
            }
        }
        float var = ssd * (1.f / 97.f);
        g_geo[(size_t)(b * NN + n) * NK + k] = 1.f / (1.f + 100.f * var);
    }
}

// -------- softmax-combine -> refined warp --------
__global__ void combine_kernel(float* __restrict__ outRW) {
    int t = blockIdx.x * blockDim.x + threadIdx.x;
    if (t >= NB * NN) return;
    size_t base = (size_t)t * NK;
    float c[NK]; float m = -FLT_MAX;
#pragma unroll
    for (int k = 0; k < NK; k++) {
        c[k] = g_tkv[base + k] + 1.5f * g_geo[base + k];
        m = fmaxf(m, c[k]);
    }
    float sw = 0.f, rx = 0.f, ry = 0.f;
#pragma unroll
    for (int k = 0; k < NK; k++) {
        float w = expf((c[k] - m) * 20.f);
        sw += w;
        rx += g_tkp[(base + k) * 2]     * w;
        ry += g_tkp[(base + k) * 2 + 1] * w;
    }
    outRW[(size_t)t * 2]     = rx / sw;
    outRW[(size_t)t * 2 + 1] = ry / sw;
}

extern "C" void kernel_launch(void* const* d_in, const int* in_sizes, int n_in,
                              void* d_out, int out_size) {
    const float* fA = (const float*)d_in[0];
    const float* fB = (const float*)d_in[1];
    const float* pA = (const float*)d_in[2];
    const float* pB = (const float*)d_in[3];
    (void)in_sizes; (void)n_in; (void)out_size;

    float* out = (float*)d_out;
    float* out_rw  = out;                          // [2,4096,2]
    float* out_ent = out + NB * NN * 2;            // [2,4096]
    float* out_sim = out + NB * NN * 2 + NB * NN;  // [2,4096,4096]

    normalize_kernel<<<(2 * NB * NN * 32 + 255) / 256, 256>>>(fA, fB);
    gemm_kernel<<<dim3(NN / BM, NN / BN, NB), 256>>>(out_sim);
    finalize_u_kernel<<<(NB * (NN + 1) + 255) / 256, 256>>>();
    // u1 fused above; remaining: v1, (u,v) x4
    sink_v_kernel<<<dim3(NN + 1, NB), 256>>>();
    for (int it = 0; it < 4; it++) {
        sink_u_kernel<<<dim3(NN + 1, NB), 256>>>(out_sim);
        sink_v_kernel<<<dim3(NN + 1, NB), 256>>>();
    }
    row_final_kernel<<<dim3(NN, NB), 256>>>(out_sim, pB, out_ent);
    geo_kernel<<<dim3(NK, NB), 256>>>(pA);
    combine_kernel<<<(NB * NN + 255) / 256, 256>>>(out_rw);
}

// round 7
// speedup vs baseline: 1.4055x; 1.1044x over previous
#include <cuda_runtime.h>
#include <cuda_bf16.h>
#include <cstdint>
#include <math.h>
#include <float.h>

#define NB 2
#define NN 4096
#define NC 128
#define NK 8
#define UVS 4100   // padded stride for u/v so each batch slice is 16B-aligned
#define KS 768     // 6-term split: A=[h|m|h|l|h|m], B=[h|h|m|h|l|m]

#define NORMC  (-9.010913347279289f)   // -log(8192)
#define LOGMC  (-0.6931471805599453f)  // log(4096) - log(8192)

// -------- scratch (static device globals; no allocation) --------
__device__ __nv_bfloat16 g_Ah[(size_t)NB * NN * KS];
__device__ __nv_bfloat16 g_Bh[(size_t)NB * NN * KS];
__device__ float g_ST[(size_t)NB * NN * NN];   // 20 * sim^T  (134 MB)
__device__ float g_u[NB * UVS];
__device__ float g_v[NB * UVS];
__device__ float g_part[(size_t)NB * NN * 32];
__device__ float g_tkv[NB * NN * NK];
__device__ float g_tkp[NB * NN * NK * 2];
__device__ float g_geo[NB * NN * NK];

// -------- reduction helpers --------
__device__ __forceinline__ float warpMaxF(float v) {
#pragma unroll
    for (int o = 16; o; o >>= 1) v = fmaxf(v, __shfl_xor_sync(0xffffffffu, v, o));
    return v;
}
__device__ __forceinline__ float warpSumF(float v) {
#pragma unroll
    for (int o = 16; o; o >>= 1) v += __shfl_xor_sync(0xffffffffu, v, o);
    return v;
}
__device__ __forceinline__ float blockReduceMax(float v, float* sw) {
    v = warpMaxF(v);
    int wid = threadIdx.x >> 5, lane = threadIdx.x & 31;
    __syncthreads();
    if (lane == 0) sw[wid] = v;
    __syncthreads();
    if (wid == 0) {
        float x = (lane < 8) ? sw[lane] : -FLT_MAX;
        x = warpMaxF(x);
        if (lane == 0) sw[0] = x;
    }
    __syncthreads();
    return sw[0];
}
__device__ __forceinline__ float blockReduceSum(float v, float* sw) {
    v = warpSumF(v);
    int wid = threadIdx.x >> 5, lane = threadIdx.x & 31;
    __syncthreads();
    if (lane == 0) sw[wid] = v;
    __syncthreads();
    if (wid == 0) {
        float x = (lane < 8) ? sw[lane] : 0.f;
        x = warpSumF(x);
        if (lane == 0) sw[0] = x;
    }
    __syncthreads();
    return sw[0];
}

// -------- mma helpers --------
__device__ __forceinline__ uint32_t smem_u32(const void* p) {
    return (uint32_t)__cvta_generic_to_shared(p);
}
__device__ __forceinline__ void ldsm_x4(uint32_t& r0, uint32_t& r1, uint32_t& r2,
                                        uint32_t& r3, uint32_t addr) {
    asm volatile("ldmatrix.sync.aligned.m8n8.x4.shared.b16 {%0,%1,%2,%3}, [%4];"
                 : "=r"(r0), "=r"(r1), "=r"(r2), "=r"(r3) : "r"(addr));
}
__device__ __forceinline__ void mma16816(float* d, const uint32_t* a, const uint32_t* b) {
    asm volatile(
        "mma.sync.aligned.m16n8k16.row.col.f32.bf16.bf16.f32 "
        "{%0,%1,%2,%3}, {%4,%5,%6,%7}, {%8,%9}, {%0,%1,%2,%3};"
        : "+f"(d[0]), "+f"(d[1]), "+f"(d[2]), "+f"(d[3])
        : "r"(a[0]), "r"(a[1]), "r"(a[2]), "r"(a[3]), "r"(b[0]), "r"(b[1]));
}

// -------- row L2 normalize + bf16 3-limb split (h+m+l = v, ~exact) --------
// A chunks: [h | m | h | l | h | m],  B chunks: [h | h | m | h | l | m]
// => sum of products = hh'+mh'+hm'+lh'+hl'+mm'  (missing terms ~2^-25)
__global__ void __launch_bounds__(256) normalize_kernel(const float* __restrict__ fA,
                                                        const float* __restrict__ fB) {
    int gw = (blockIdx.x * blockDim.x + threadIdx.x) >> 5;
    int lane = threadIdx.x & 31;
    if (gw >= 2 * NB * NN) return;
    int row = gw & (NB * NN - 1);
    bool isA = gw < NB * NN;
    const float* src = isA ? fA : fB;
    const float* p = src + (size_t)row * NC;
    float x[4]; float ss = 0.f;
#pragma unroll
    for (int l = 0; l < 4; l++) { x[l] = p[lane + l * 32]; ss += x[l] * x[l]; }
    ss = warpSumF(ss);
    float sc = 1.f / fmaxf(sqrtf(ss), 1e-12f);
    __nv_bfloat16* q = (isA ? g_Ah : g_Bh) + (size_t)row * KS;
#pragma unroll
    for (int l = 0; l < 4; l++) {
        float v = x[l] * sc;
        __nv_bfloat16 h = __float2bfloat16(v);
        float r1 = v - __bfloat162float(h);
        __nv_bfloat16 m = __float2bfloat16(r1);
        float r2 = r1 - __bfloat162float(m);
        __nv_bfloat16 lo = __float2bfloat16(r2);
        int c = lane + l * 32;
        if (isA) {
            q[c]       = h;  q[c + 128] = m;  q[c + 256] = h;
            q[c + 384] = lo; q[c + 512] = h;  q[c + 640] = m;
        } else {
            q[c]       = h;  q[c + 128] = h;  q[c + 256] = m;
            q[c + 384] = h;  q[c + 512] = lo; q[c + 640] = m;
        }
    }
}

// -------- bf16 tensor-core GEMM (K=768, 6-term) + fused transpose + first-u --------
__global__ void __launch_bounds__(256, 2) gemm_kernel(float* __restrict__ C) {
    __shared__ __align__(16) unsigned char sm[33 * 1024];
    float* stg = (float*)sm;                   // [32][132] transpose staging
    float* pw  = (float*)(sm + 24576);         // [128][4] partial expsums

    const int b = blockIdx.z;
    const __nv_bfloat16* Ag = g_Ah + (size_t)b * NN * KS;
    const __nv_bfloat16* Bg = g_Bh + (size_t)b * NN * KS;
    float* Cb = C + (size_t)b * NN * NN;
    float* STb = g_ST + (size_t)b * NN * NN;

    int tid = threadIdx.x, lane = tid & 31, wid = tid >> 5;
    int m_w = (wid & 1) * 64, n_w = (wid >> 1) * 32;
    int m0 = blockIdx.x * 128, n0 = blockIdx.y * 128;
    uint32_t smA = smem_u32(sm), smB = smA + 16384;

    float acc[4][4][4];
#pragma unroll
    for (int i = 0; i < 4; i++)
#pragma unroll
        for (int j = 0; j < 4; j++)
#pragma unroll
            for (int e = 0; e < 4; e++) acc[i][j][e] = 0.f;

    for (int kc = 0; kc < 12; kc++) {
        // load 128x64 bf16 chunks of A and B, swizzled 128B rows
#pragma unroll
        for (int q = tid; q < 2048; q += 256) {
            int isB = q >= 1024;
            int qq = q & 1023;
            int row = qq >> 3, c16 = qq & 7;
            const __nv_bfloat16* srcp = isB ? Bg : Ag;
            int grow = (isB ? n0 : m0) + row;
            uint4 w = *(const uint4*)&srcp[(size_t)grow * KS + kc * 64 + c16 * 8];
            int sw = (c16 * 16) ^ ((row & 7) * 16);
            *(uint4*)(sm + isB * 16384 + row * 128 + sw) = w;
        }
        __syncthreads();
#pragma unroll
        for (int ks = 0; ks < 4; ks++) {
            int kb = ks * 16;
            uint32_t a[4][4], bfr[4][2];
#pragma unroll
            for (int mi = 0; mi < 4; mi++) {
                int row = m_w + mi * 16 + (lane & 15);
                int col = kb + ((lane >> 4) << 3);
                uint32_t addr = smA + row * 128 + ((col * 2) ^ ((row & 7) * 16));
                ldsm_x4(a[mi][0], a[mi][1], a[mi][2], a[mi][3], addr);
            }
#pragma unroll
            for (int g = 0; g < 2; g++) {
                int row = n_w + g * 16 + ((lane >> 4) << 3) + (lane & 7);
                int col = kb + ((lane >> 3) & 1) * 8;
                uint32_t addr = smB + row * 128 + ((col * 2) ^ ((row & 7) * 16));
                uint32_t r0, r1, r2, r3;
                ldsm_x4(r0, r1, r2, r3, addr);
                bfr[2 * g][0] = r0; bfr[2 * g][1] = r1;
                bfr[2 * g + 1][0] = r2; bfr[2 * g + 1][1] = r3;
            }
#pragma unroll
            for (int mi = 0; mi < 4; mi++)
#pragma unroll
                for (int ni = 0; ni < 4; ni++)
                    mma16816(acc[mi][ni], a[mi], bfr[ni]);
        }
        __syncthreads();
    }

    int r0l = lane >> 2, c0l = (lane & 3) * 2;
    // ---- sim store ----
#pragma unroll
    for (int mi = 0; mi < 4; mi++)
#pragma unroll
        for (int hf = 0; hf < 2; hf++) {
            int r = m_w + mi * 16 + r0l + hf * 8;
            size_t ro = (size_t)(m0 + r) * NN + n0 + n_w;
#pragma unroll
            for (int ni = 0; ni < 4; ni++) {
                float2 v = make_float2(acc[mi][ni][hf * 2], acc[mi][ni][hf * 2 + 1]);
                *(float2*)&Cb[ro + ni * 8 + c0l] = v;
            }
        }
    // ---- first-u partials ----
#pragma unroll
    for (int mi = 0; mi < 4; mi++)
#pragma unroll
        for (int hf = 0; hf < 2; hf++) {
            float s = 0.f;
#pragma unroll
            for (int ni = 0; ni < 4; ni++) {
                s += __expf(fmaf(20.f, acc[mi][ni][hf * 2], -20.f));
                s += __expf(fmaf(20.f, acc[mi][ni][hf * 2 + 1], -20.f));
            }
            s += __shfl_xor_sync(0xffffffffu, s, 1);
            s += __shfl_xor_sync(0xffffffffu, s, 2);
            if ((lane & 3) == 0)
                pw[(m_w + mi * 16 + r0l + hf * 8) * 4 + (wid >> 1)] = s;
        }
    __syncthreads();
    if (tid < 128) {
        float s = pw[tid * 4] + pw[tid * 4 + 1] + pw[tid * 4 + 2] + pw[tid * 4 + 3];
        g_part[((size_t)(b * NN + m0 + tid)) * 32 + blockIdx.y] = s;
    }
    // ---- 20*sim^T via smem staging (coalesced 512B rows) ----
    for (int ch = 0; ch < 4; ch++) {
        __syncthreads();
        if ((wid >> 1) == ch) {
#pragma unroll
            for (int mi = 0; mi < 4; mi++)
#pragma unroll
                for (int ni = 0; ni < 4; ni++) {
                    int nl = ni * 8 + c0l;
                    int m = m_w + mi * 16 + r0l;
                    stg[nl * 132 + m]           = 20.f * acc[mi][ni][0];
                    stg[(nl + 1) * 132 + m]     = 20.f * acc[mi][ni][1];
                    stg[nl * 132 + m + 8]       = 20.f * acc[mi][ni][2];
                    stg[(nl + 1) * 132 + m + 8] = 20.f * acc[mi][ni][3];
                }
        }
        __syncthreads();
#pragma unroll
        for (int q = tid; q < 1024; q += 256) {
            int rowq = q >> 5, c4 = (q & 31) * 4;
            float4 w = *(float4*)&stg[rowq * 132 + c4];
            *(float4*)&STb[(size_t)(n0 + ch * 32 + rowq) * NN + m0 + c4] = w;
        }
    }
}

// -------- finalize fused first u-update --------
__global__ void finalize_u_kernel() {
    int t = blockIdx.x * blockDim.x + threadIdx.x;
    if (t >= NB * (NN + 1)) return;
    int b = t / (NN + 1), r = t % (NN + 1);
    float u;
    if (r < NN) {
        const float* p = g_part + ((size_t)(b * NN + r)) * 32;
        float s = __expf(-20.f);
#pragma unroll
        for (int k = 0; k < 32; k++) s += p[k];
        u = NORMC - (20.f + __logf(s));
    } else {
        u = LOGMC - __logf((float)(NN + 1));
    }
    g_u[b * UVS + r] = u;
}

// -------- Sinkhorn u-update (vectorized) --------
__global__ void __launch_bounds__(256) sink_u_kernel(const float* __restrict__ sim) {
    __shared__ float sw[32];
    int r = blockIdx.x, b = blockIdx.y, tid = threadIdx.x;
    const float* vv = g_v + b * UVS;
    const float4* vv4 = (const float4*)vv;
    float4 tv[4];
    float m = -FLT_MAX;
    if (r < NN) {
        const float4* s4 = (const float4*)(sim + (size_t)b * NN * NN + (size_t)r * NN);
#pragma unroll
        for (int k = 0; k < 4; k++) {
            int idx = tid + (k << 8);
            float4 s = s4[idx], v = vv4[idx];
            tv[k].x = fmaf(20.f, s.x, v.x); tv[k].y = fmaf(20.f, s.y, v.y);
            tv[k].z = fmaf(20.f, s.z, v.z); tv[k].w = fmaf(20.f, s.w, v.w);
            m = fmaxf(m, fmaxf(fmaxf(tv[k].x, tv[k].y), fmaxf(tv[k].z, tv[k].w)));
        }
    } else {
#pragma unroll
        for (int k = 0; k < 4; k++) {
            tv[k] = vv4[tid + (k << 8)];
            m = fmaxf(m, fmaxf(fmaxf(tv[k].x, tv[k].y), fmaxf(tv[k].z, tv[k].w)));
        }
    }
    float extra = (tid == 0) ? vv[NN] : -FLT_MAX;
    m = fmaxf(m, extra);
    float M = blockReduceMax(m, sw);
    float s = 0.f;
#pragma unroll
    for (int k = 0; k < 4; k++)
        s += __expf(tv[k].x - M) + __expf(tv[k].y - M)
           + __expf(tv[k].z - M) + __expf(tv[k].w - M);
    if (tid == 0) s += __expf(extra - M);
    float S = blockReduceSum(s, sw);
    if (tid == 0)
        g_u[b * UVS + r] = ((r < NN) ? NORMC : LOGMC) - (M + __logf(S));
}

// -------- Sinkhorn v-update (vectorized; ST holds 20*sim^T) --------
__global__ void __launch_bounds__(256) sink_v_kernel() {
    __shared__ float sw[32];
    int r = blockIdx.x, b = blockIdx.y, tid = threadIdx.x;
    const float* uu = g_u + b * UVS;
    const float4* uu4 = (const float4*)uu;
    float4 tv[4];
    float m = -FLT_MAX;
    if (r < NN) {
        const float4* s4 = (const float4*)(g_ST + (size_t)b * NN * NN + (size_t)r * NN);
#pragma unroll
        for (int k = 0; k < 4; k++) {
            int idx = tid + (k << 8);
            float4 s = s4[idx], u = uu4[idx];
            tv[k].x = s.x + u.x; tv[k].y = s.y + u.y;
            tv[k].z = s.z + u.z; tv[k].w = s.w + u.w;
            m = fmaxf(m, fmaxf(fmaxf(tv[k].x, tv[k].y), fmaxf(tv[k].z, tv[k].w)));
        }
    } else {
#pragma unroll
        for (int k = 0; k < 4; k++) {
            tv[k] = uu4[tid + (k << 8)];
            m = fmaxf(m, fmaxf(fmaxf(tv[k].x, tv[k].y), fmaxf(tv[k].z, tv[k].w)));
        }
    }
    float extra = (tid == 0) ? uu[NN] : -FLT_MAX;
    m = fmaxf(m, extra);
    float M = blockReduceMax(m, sw);
    float s = 0.f;
#pragma unroll
    for (int k = 0; k < 4; k++)
        s += __expf(tv[k].x - M) + __expf(tv[k].y - M)
           + __expf(tv[k].z - M) + __expf(tv[k].w - M);
    if (tid == 0) s += __expf(extra - M);
    float S = blockReduceSum(s, sw);
    if (tid == 0)
        g_v[b * UVS + r] = ((r < NN) ? NORMC : LOGMC) - (M + __logf(S));
}

// -------- per-row: entropy + top-8 --------
__global__ void __launch_bounds__(256) row_final_kernel(const float* __restrict__ sim,
                                                        const float* __restrict__ posB,
                                                        float* __restrict__ ent_out) {
    __shared__ float a[NN];
    __shared__ float sw[32];
    __shared__ int   swi[32];
    __shared__ float s_bv;
    __shared__ int   s_bi;
    int r = blockIdx.x, b = blockIdx.y, tid = threadIdx.x;
    const float4* vv4 = (const float4*)(g_v + b * UVS);
    const float4* s4 = (const float4*)(sim + (size_t)b * NN * NN + (size_t)r * NN);
    float ui = g_u[b * UVS + r];
    float4 tv[4];
#pragma unroll
    for (int k = 0; k < 4; k++) {
        int idx = tid + (k << 8);
        float4 s = s4[idx], v = vv4[idx];
        tv[k].x = fmaf(20.f, s.x, v.x); tv[k].y = fmaf(20.f, s.y, v.y);
        tv[k].z = fmaf(20.f, s.z, v.z); tv[k].w = fmaf(20.f, s.w, v.w);
        ((float4*)a)[idx] = tv[k];
    }
    float s = 0.f, e = 0.f;
#pragma unroll
    for (int k = 0; k < 4; k++) {
        s += __expf(tv[k].x + ui) + __expf(tv[k].y + ui)
           + __expf(tv[k].z + ui) + __expf(tv[k].w + ui);
    }
    float S = blockReduceSum(s, sw);
    float inv = 1.f / (S + 1e-8f);
#pragma unroll
    for (int k = 0; k < 4; k++) {
        float p;
        p = __expf(tv[k].x + ui) * inv; e -= p * __logf(p + 1e-8f);
        p = __expf(tv[k].y + ui) * inv; e -= p * __logf(p + 1e-8f);
        p = __expf(tv[k].z + ui) * inv; e -= p * __logf(p + 1e-8f);
        p = __expf(tv[k].w + ui) * inv; e -= p * __logf(p + 1e-8f);
    }
    float E = blockReduceSum(e, sw);
    if (tid == 0) ent_out[b * NN + r] = E;
    __syncthreads();
    long base = ((long)(b * NN + r)) * NK;
    int wid = tid >> 5, lane = tid & 31;
    for (int t = 0; t < NK; t++) {
        float bv = -FLT_MAX; int bi = 0;
#pragma unroll
        for (int k = 0; k < 16; k++) {
            int j = tid + (k << 8);
            float x = a[j];
            if (x > bv) { bv = x; bi = j; }
        }
#pragma unroll
        for (int o = 16; o; o >>= 1) {
            float ov = __shfl_xor_sync(0xffffffffu, bv, o);
            int   oi = __shfl_xor_sync(0xffffffffu, bi, o);
            if (ov > bv || (ov == bv && oi < bi)) { bv = ov; bi = oi; }
        }
        __syncthreads();
        if (lane == 0) { sw[wid] = bv; swi[wid] = bi; }
        __syncthreads();
        if (wid == 0) {
            float x = (lane < 8) ? sw[lane] : -FLT_MAX;
            int  xi = (lane < 8) ? swi[lane] : 0;
#pragma unroll
            for (int o = 4; o; o >>= 1) {
                float ov = __shfl_xor_sync(0xffffffffu, x, o);
                int   oi = __shfl_xor_sync(0xffffffffu, xi, o);
                if (ov > x || (ov == x && oi < xi)) { x = ov; xi = oi; }
            }
            if (lane == 0) { s_bv = x; s_bi = xi; }
        }
        __syncthreads();
        if (tid == 0) {
            int idx = s_bi;
            g_tkv[base + t] = expf(s_bv + ui);
            float px = posB[((size_t)b * NN + idx) * 2];
            float py = posB[((size_t)b * NN + idx) * 2 + 1];
            g_tkp[(base + t) * 2]     = px;
            g_tkp[(base + t) * 2 + 1] = py;
            a[idx] = -FLT_MAX;
        }
        __syncthreads();
    }
}

// -------- 7x7 local displacement variance (split over 4 z-slices) --------
__global__ void __launch_bounds__(256) geo_kernel(const float* __restrict__ posA) {
    __shared__ float dx[NN];
    __shared__ float dy[NN];
    int k = blockIdx.x, b = blockIdx.y, z = blockIdx.z, tid = threadIdx.x;
    for (int n = tid; n < NN; n += 256) {
        size_t tp = ((size_t)(b * NN + n) * NK + k) * 2;
        size_t pp = ((size_t)b * NN + n) * 2;
        dx[n] = g_tkp[tp]     - posA[pp];
        dy[n] = g_tkp[tp + 1] - posA[pp + 1];
    }
    __syncthreads();
    for (int n = z * 1024 + tid; n < (z + 1) * 1024; n += 256) {
        int h = n >> 6, w = n & 63;
        float s = 0.f; int cnt = 0;
        for (int di = -3; di <= 3; di++) {
            int hh = h + di;
            if ((unsigned)hh >= 64u) continue;
            for (int dj = -3; dj <= 3; dj++) {
                int ww = w + dj;
                if ((unsigned)ww >= 64u) continue;
                int m = hh * 64 + ww;
                s += dx[m] + dy[m];
                cnt += 2;
            }
        }
        float mean = s * (1.f / 98.f);
        float ssd = (float)(98 - cnt) * mean * mean;
        for (int di = -3; di <= 3; di++) {
            int hh = h + di;
            if ((unsigned)hh >= 64u) continue;
            for (int dj = -3; dj <= 3; dj++) {
                int ww = w + dj;
                if ((unsigned)ww >= 64u) continue;
                int m = hh * 64 + ww;
                float ax = dx[m] - mean, ay = dy[m] - mean;
                ssd += ax * ax + ay * ay;
            }
        }
        float var = ssd * (1.f / 97.f);
        g_geo[(size_t)(b * NN + n) * NK + k] = 1.f / (1.f + 100.f * var);
    }
}

// -------- softmax-combine -> refined warp --------
__global__ void combine_kernel(float* __restrict__ outRW) {
    int t = blockIdx.x * blockDim.x + threadIdx.x;
    if (t >= NB * NN) return;
    size_t base = (size_t)t * NK;
    float c[NK]; float m = -FLT_MAX;
#pragma unroll
    for (int k = 0; k < NK; k++) {
        c[k] = g_tkv[base + k] + 1.5f * g_geo[base + k];
        m = fmaxf(m, c[k]);
    }
    float sw = 0.f, rx = 0.f, ry = 0.f;
#pragma unroll
    for (int k = 0; k < NK; k++) {
        float w = expf((c[k] - m) * 20.f);
        sw += w;
        rx += g_tkp[(base + k) * 2]     * w;
        ry += g_tkp[(base + k) * 2 + 1] * w;
    }
    outRW[(size_t)t * 2]     = rx / sw;
    outRW[(size_t)t * 2 + 1] = ry / sw;
}

extern "C" void kernel_launch(void* const* d_in, const int* in_sizes, int n_in,
                              void* d_out, int out_size) {
    const float* fA = (const float*)d_in[0];
    const float* fB = (const float*)d_in[1];
    const float* pA = (const float*)d_in[2];
    const float* pB = (const float*)d_in[3];
    (void)in_sizes; (void)n_in; (void)out_size;

    float* out = (float*)d_out;
    float* out_rw  = out;                          // [2,4096,2]
    float* out_ent = out + NB * NN * 2;            // [2,4096]
    float* out_sim = out + NB * NN * 2 + NB * NN;  // [2,4096,4096]

    normalize_kernel<<<(2 * NB * NN * 32 + 255) / 256, 256>>>(fA, fB);
    gemm_kernel<<<dim3(32, 32, NB), 256>>>(out_sim);
    finalize_u_kernel<<<(NB * (NN + 1) + 255) / 256, 256>>>();
    sink_v_kernel<<<dim3(NN + 1, NB), 256>>>();
    for (int it = 0; it < 4; it++) {
        sink_u_kernel<<<dim3(NN + 1, NB), 256>>>(out_sim);
        sink_v_kernel<<<dim3(NN + 1, NB), 256>>>();
    }
    row_final_kernel<<<dim3(NN, NB), 256>>>(out_sim, pB, out_ent);
    geo_kernel<<<dim3(NK, NB, 4), 256>>>(pA);
    combine_kernel<<<(NB * NN + 255) / 256, 256>>>(out_rw);
}